// round 13
// baseline (speedup 1.0000x reference)
#include <cuda_runtime.h>
#include <cstdint>

// TitansMemory B=16 L=8192 DK=DV=128 — v7: R8 2-rows/warp layout + R12
// pipelined-fold correction (both validated). Per step: 4 raw dots vs
// PRE-update state folded in 5 shfl (16-lane classify tree) + t-fetch +
// r-broadcast = 7 shfl/warp-step serving 2 rows. Per-chunk skq/G/H prep
// via a 16-value transpose-reduction tree (16 shfl).
// 256 CTAs x 128 thr (4 warps, 8 rows), 2 CTAs/SM.

#define CSTEPS 16
#define L_SEQ  8192
#define NCH    (L_SEQ / CSTEPS)
#define DK     128

using ull = unsigned long long;

__device__ __forceinline__ ull pk(float lo, float hi) {
    ull r; asm("mov.b64 %0,{%1,%2};" : "=l"(r) : "f"(lo), "f"(hi)); return r;
}
__device__ __forceinline__ float hadd2(ull p) {
    float lo, hi; asm("mov.b64 {%0,%1},%2;" : "=f"(lo), "=f"(hi) : "l"(p));
    return lo + hi;
}
__device__ __forceinline__ ull mul2(ull a, ull b) {
    ull d; asm("mul.rn.f32x2 %0,%1,%2;" : "=l"(d) : "l"(a), "l"(b)); return d;
}
__device__ __forceinline__ ull fma2(ull a, ull b, ull c) {
    ull d; asm("fma.rn.f32x2 %0,%1,%2,%3;" : "=l"(d) : "l"(a), "l"(b), "l"(c)); return d;
}
__device__ __forceinline__ ull add2(ull a, ull b) {
    ull d; asm("add.rn.f32x2 %0,%1,%2;" : "=l"(d) : "l"(a), "l"(b)); return d;
}
__device__ __forceinline__ unsigned su32(const void* p) {
    return (unsigned)__cvta_generic_to_shared(p);
}
__device__ __forceinline__ void cp16(unsigned s, const void* g) {
    asm volatile("cp.async.cg.shared.global [%0],[%1],16;" :: "r"(s), "l"(g));
}
__device__ __forceinline__ void cp4(unsigned s, const void* g) {
    asm volatile("cp.async.ca.shared.global [%0],[%1],4;" :: "r"(s), "l"(g));
}
__device__ __forceinline__ void cp_commit() {
    asm volatile("cp.async.commit_group;" ::: "memory");
}
__device__ __forceinline__ void cp_wait_all() {
    asm volatile("cp.async.wait_group 0;" ::: "memory");
}
__device__ __forceinline__ float dot4(float4 a, float4 b) {
    return fmaf(a.x, b.x, fmaf(a.y, b.y, fmaf(a.z, b.z, a.w * b.w)));
}
// even/odd float4-chunk permutation: lane g reads slots g,16+g = floats 8g..8g+7
__device__ __forceinline__ int perm(int c) { return (c >> 1) | ((c & 1) << 4); }

__global__ __launch_bounds__(128, 2)
void titans_kernel(const float* __restrict__ Q,
                   const float* __restrict__ K,
                   const float* __restrict__ V,
                   float* __restrict__ Y) {
    static constexpr float cCP[16] = {  // 0.98^i
        1.0f, 0.98f, 0.9604f, 0.941192f, 0.92236816f, 0.9039207968f,
        0.8858423809f, 0.8681255332f, 0.8507630226f, 0.8337477621f,
        0.8170728069f, 0.8007313508f, 0.7847167237f, 0.7690223892f,
        0.7536419414f, 0.7385691035f };
    static constexpr float cCY[16] = {  // 0.98^(i+1)
        0.98f, 0.9604f, 0.941192f, 0.92236816f, 0.9039207968f, 0.8858423809f,
        0.8681255332f, 0.8507630226f, 0.8337477621f, 0.8170728069f,
        0.8007313508f, 0.7847167237f, 0.7690223892f, 0.7536419414f,
        0.7385691035f, 0.7237977214f };
    static constexpr float cS[16] = {   // -0.1*(0.9/0.98)^(i+1)
        -0.09183673469f, -0.08433985839f, -0.07745414463f, -0.07113064017f,
        -0.06532344097f, -0.05999029968f, -0.05509252418f, -0.05059456302f,
        -0.04646378542f, -0.04267021926f, -0.03918632342f, -0.03598663375f,
        -0.03304811221f, -0.03034970510f, -0.02787207213f, -0.02559670445f };
    static constexpr float cA[16] = {   // -0.02/0.98^(i+1)
        -0.02040816327f, -0.02082465640f, -0.02124964939f, -0.02168331570f,
        -0.02212583235f, -0.02257738015f, -0.02303814301f, -0.02350830920f,
        -0.02398807061f, -0.02447762307f, -0.02497716640f, -0.02548690449f,
        -0.02600704540f, -0.02653780143f, -0.02707938921f, -0.02763202981f };
    static constexpr float cB[16] = {   // 0.2/0.9^(i+1)
        0.2222222222f, 0.2469135802f, 0.2743484225f, 0.3048315805f,
        0.3387017561f, 0.3763352846f, 0.4181503162f, 0.4646114624f,
        0.5162349582f, 0.5735943980f, 0.6373271089f, 0.7081412321f,
        0.7868235912f, 0.8742484347f, 0.9713871497f, 1.0793190552f };
    constexpr float C16F = 0.7237977214f;   // 0.98^16
    constexpr float B16F = 0.1853020189f;   // 0.9^16

    __shared__ float kb[2][CSTEPS][DK];      // slot-swizzled
    __shared__ float qb[2][CSTEPS][DK];
    __shared__ float vT[2][8][20];           // [row][step]
    __shared__ float yb[2][CSTEPS][8];       // [step][row]
    __shared__ float skqs[16];               // k_t.q_t
    __shared__ float Gs[16];                 // k_j.k_{j+1}, j<15
    __shared__ float Hs[16];                 // k_j.q_{j+1}, j<15

    const int tid  = threadIdx.x;
    const int w    = tid >> 5;               // warp 0..3
    const int lane = tid & 31;
    const int g    = lane & 15;              // pos within 16-lane group
    const int half = lane >> 4;
    const int row  = (w << 1) + half;        // 0..7

    const int b     = blockIdx.x >> 4;       // 16 batches
    const int vbase = (blockIdx.x & 15) << 3;// 16 groups x 8 rows

    const size_t base = (size_t)b * L_SEQ * DK;
    const float* gk = K + base;
    const float* gq = Q + base;
    const float* gv = V + base;
    float*       gy = Y + base;

    // state: lane owns What[row, 8g..8g+7], mhat same (4 f32x2 pairs each)
    ull W0 = 0, W1 = 0, W2 = 0, W3 = 0;
    ull M0 = 0, M1 = 0, M2 = 0, M3 = 0;

    const bool fb0 = lane & 1;
    const bool fb1 = lane & 2;
    const int  src0 = lane & 28;             // class-0 lane of own 4-group
    const float* corrT = ((lane & 3) < 2) ? Gs : Hs;

    // ---- preload chunk 0 (swizzled) ----
    {
        #pragma unroll
        for (int u = 0; u < 4; ++u) {
            int id = u * 128 + tid;          // t = id>>5, c = id&31
            int t = id >> 5, c = id & 31;
            cp16(su32(&kb[0][t][perm(c) * 4]), gk + t * DK + c * 4);
            cp16(su32(&qb[0][t][perm(c) * 4]), gq + t * DK + c * 4);
        }
        {
            int i = tid >> 3, j = tid & 7;
            cp4(su32(&vT[0][j][i]), gv + (size_t)i * DK + vbase + j);
        }
        cp_commit();
        cp_wait_all();
        __syncthreads();
    }

    for (int chunk = 0; chunk < NCH; ++chunk) {
        const int cur = chunk & 1;
        const int t0  = chunk * CSTEPS;

        // ---- prep: warp w computes skq/G/H for steps 4w..4w+3 ----
        {
            float acc[16];
            #pragma unroll
            for (int j = 0; j < 4; ++j) {
                const int i  = 4 * w + j;
                const int i1 = (i + 1 < 16) ? i + 1 : 15;  // i=15 discarded
                const float4 ki  = *(const float4*)&kb[cur][i ][lane << 2];
                const float4 qi  = *(const float4*)&qb[cur][i ][lane << 2];
                const float4 ki1 = *(const float4*)&kb[cur][i1][lane << 2];
                const float4 qi1 = *(const float4*)&qb[cur][i1][lane << 2];
                acc[j]     = dot4(ki, qi);
                acc[4 + j] = dot4(ki, ki1);
                acc[8 + j] = dot4(ki, qi1);
            }
            #pragma unroll
            for (int j = 12; j < 16; ++j) acc[j] = 0.0f;

            // transpose-reduction tree: value v ends at lanes {2v, 2v+1}
            const bool t4 = lane & 16, t3 = lane & 8, t2 = lane & 4, t1 = lane & 2;
            #pragma unroll
            for (int j = 0; j < 8; ++j) {
                float s = t4 ? acc[j] : acc[8 + j];
                float rc = __shfl_xor_sync(0xffffffffu, s, 16);
                acc[j] = (t4 ? acc[8 + j] : acc[j]) + rc;
            }
            #pragma unroll
            for (int j = 0; j < 4; ++j) {
                float s = t3 ? acc[j] : acc[4 + j];
                float rc = __shfl_xor_sync(0xffffffffu, s, 8);
                acc[j] = (t3 ? acc[4 + j] : acc[j]) + rc;
            }
            #pragma unroll
            for (int j = 0; j < 2; ++j) {
                float s = t2 ? acc[j] : acc[2 + j];
                float rc = __shfl_xor_sync(0xffffffffu, s, 4);
                acc[j] = (t2 ? acc[2 + j] : acc[j]) + rc;
            }
            {
                float s = t1 ? acc[0] : acc[1];
                float rc = __shfl_xor_sync(0xffffffffu, s, 2);
                acc[0] = (t1 ? acc[1] : acc[0]) + rc;
                acc[0] += __shfl_xor_sync(0xffffffffu, acc[0], 1);
            }
            const int vv = (lane >> 1) & 15;
            if ((lane & 1) == 0) {
                if (vv < 4) {
                    skqs[4 * w + vv] = acc[0];
                } else if (vv < 8) {
                    int s = 4 * w + vv - 4;
                    if (s < 15) Gs[s] = acc[0];
                } else if (vv < 12) {
                    int s = 4 * w + vv - 8;
                    if (s < 15) Hs[s] = acc[0];
                }
            }
        }

        // stage this thread's v row
        float vreg[CSTEPS];
        #pragma unroll
        for (int jj = 0; jj < 4; ++jj)
            *(float4*)&vreg[jj * 4] = *(const float4*)&vT[cur][row][jj * 4];

        // prefetch next chunk
        if (chunk + 1 < NCH) {
            const int nb = cur ^ 1;
            const size_t nt = (size_t)(t0 + CSTEPS) * DK;
            #pragma unroll
            for (int u = 0; u < 4; ++u) {
                int id = u * 128 + tid;
                int t = id >> 5, c = id & 31;
                cp16(su32(&kb[nb][t][perm(c) * 4]), gk + nt + t * DK + c * 4);
                cp16(su32(&qb[nb][t][perm(c) * 4]), gq + nt + t * DK + c * 4);
            }
            {
                int i = tid >> 3, j = tid & 7;
                cp4(su32(&vT[nb][j][i]), gv + nt + (size_t)i * DK + vbase + j);
            }
        }
        cp_commit();

        __syncthreads();   // skqs/Gs/Hs visible

        float skqreg[CSTEPS];
        #pragma unroll
        for (int jj = 0; jj < 4; ++jj)
            *(float4*)&skqreg[jj * 4] = *(const float4*)&skqs[jj * 4];

        // fold helper: 4 dots vs CURRENT state, 16-lane classify reduce.
        // out: c (class value: 0=Wk,1=mk,2=Wq,3=mq), t = partner class
        #define DOTS_FOLD(I, OX, OT, OK0, OK1, OK2, OK3)                        \
        {                                                                       \
            const float4 kA = *(const float4*)&kb[cur][I][g * 4];               \
            const float4 kB = *(const float4*)&kb[cur][I][64 + g * 4];          \
            const float4 qA = *(const float4*)&qb[cur][I][g * 4];               \
            const float4 qB = *(const float4*)&qb[cur][I][64 + g * 4];          \
            OK0 = pk(kA.x, kA.y); OK1 = pk(kA.z, kA.w);                         \
            OK2 = pk(kB.x, kB.y); OK3 = pk(kB.z, kB.w);                         \
            const ull q0 = pk(qA.x, qA.y), q1 = pk(qA.z, qA.w);                 \
            const ull q2 = pk(qB.x, qB.y), q3 = pk(qB.z, qB.w);                 \
            float pa = hadd2(add2(fma2(W0, OK0, mul2(W1, OK1)),                 \
                                  fma2(W2, OK2, mul2(W3, OK3))));               \
            float pb = hadd2(add2(fma2(M0, OK0, mul2(M1, OK1)),                 \
                                  fma2(M2, OK2, mul2(M3, OK3))));               \
            float pc = hadd2(add2(fma2(W0, q0, mul2(W1, q1)),                   \
                                  fma2(W2, q2, mul2(W3, q3))));                 \
            float pd = hadd2(add2(fma2(M0, q0, mul2(M1, q1)),                   \
                                  fma2(M2, q2, mul2(M3, q3))));                 \
            float x1 = fb0 ? pa : pb;                                           \
            float u1 = (fb0 ? pb : pa) + __shfl_xor_sync(0xffffffffu, x1, 1);   \
            float x2 = fb0 ? pc : pd;                                           \
            float u2 = (fb0 ? pd : pc) + __shfl_xor_sync(0xffffffffu, x2, 1);   \
            float x3 = fb1 ? u1 : u2;                                           \
            float cc = (fb1 ? u2 : u1) + __shfl_xor_sync(0xffffffffu, x3, 2);   \
            cc += __shfl_xor_sync(0xffffffffu, cc, 4);                          \
            cc += __shfl_xor_sync(0xffffffffu, cc, 8);                          \
            OX = cc;                                                            \
            OT = __shfl_xor_sync(0xffffffffu, cc, 1);                           \
        }

        // pre-loop: dots+fold for step 0 vs chunk-start state
        float x, t;
        ull kc0, kc1, kc2, kc3;
        DOTS_FOLD(0, x, t, kc0, kc1, kc2, kc3)

        float rprev = 0.0f;

        // ---- 16 sequential steps ----
        #pragma unroll
        for (int i = 0; i < CSTEPS; ++i) {
            // correct pre-state dots with r_{i-1}
            float e1, e2;
            if (i == 0) {
                e1 = x; e2 = t;
            } else {
                const float Vv = corrT[i - 1];
                const float zc = cA[i - 1] * rprev;
                const float zb = cB[i - 1] * rprev;
                e1 = fmaf(cS[i - 1], t, x);
                e1 = fmaf(zc, Vv, e1);
                e2 = fmaf(zb, Vv, t);
            }
            const float rloc = fmaf(cCP[i], e1, -vreg[i]);
            const float r    = __shfl_sync(0xffffffffu, rloc, src0);
            const float ta = cA[i] * r;
            const float tb = cB[i] * r;

            // y from class-2 lane of each 16-lane group
            if ((lane & 15) == 2)
                yb[cur][i][row] = cCY[i] *
                    fmaf(ta, skqreg[i], fmaf(cS[i], e2, e1));

            // next step's dots+fold vs PRE-update state
            float nx = 0.0f, nt = 0.0f;
            ull kn0 = 0, kn1 = 0, kn2 = 0, kn3 = 0;
            if (i + 1 < CSTEPS) {
                DOTS_FOLD(i + 1, nx, nt, kn0, kn1, kn2, kn3)
            }

            // update step i (W uses pre-update m), k_i in kc regs
            const ull a2 = pk(ta, ta), b2 = pk(tb, tb), s2 = pk(cS[i], cS[i]);
            W0 = fma2(s2, M0, W0); W0 = fma2(a2, kc0, W0); M0 = fma2(b2, kc0, M0);
            W1 = fma2(s2, M1, W1); W1 = fma2(a2, kc1, W1); M1 = fma2(b2, kc1, M1);
            W2 = fma2(s2, M2, W2); W2 = fma2(a2, kc2, W2); M2 = fma2(b2, kc2, M2);
            W3 = fma2(s2, M3, W3); W3 = fma2(a2, kc3, W3); M3 = fma2(b2, kc3, M3);

            rprev = r;
            x = nx; t = nt;
            kc0 = kn0; kc1 = kn1; kc2 = kn2; kc3 = kn3;
        }
        #undef DOTS_FOLD

        // chunk-end rescale
        {
            const ull c16 = pk(C16F, C16F);
            const ull b16 = pk(B16F, B16F);
            W0 = mul2(c16, W0); W1 = mul2(c16, W1);
            W2 = mul2(c16, W2); W3 = mul2(c16, W3);
            M0 = mul2(b16, M0); M1 = mul2(b16, M1);
            M2 = mul2(b16, M2); M3 = mul2(b16, M3);
        }

        cp_wait_all();
        __syncthreads();

        // writeback this chunk's y
        {
            int i = tid >> 3, j = tid & 7;
            gy[(size_t)(t0 + i) * DK + vbase + j] = yb[cur][i][j];
        }
    }
}

extern "C" void kernel_launch(void* const* d_in, const int* in_sizes, int n_in,
                              void* d_out, int out_size) {
    const float* Q = (const float*)d_in[0];
    const float* K = (const float*)d_in[1];
    const float* V = (const float*)d_in[2];
    float* Y = (float*)d_out;
    (void)in_sizes; (void)n_in; (void)out_size;
    titans_kernel<<<256, 128>>>(Q, K, V, Y);
}

// round 14
// speedup vs baseline: 1.2720x; 1.2720x over previous
#include <cuda_runtime.h>
#include <cstdint>

// TitansMemory B=16 L=8192 DK=DV=128 — v8: R10 skeleton (validated, 1725us)
// with MIO-count reduction. 1 row/warp, folded 3-value butterfly (5 shfl) +
// 1 r-broadcast; y written as 3 pre-scaled partials via one predicated STS
// (summed at writeback) -> 6 shfl/step vs 8. 256 CTAs x 256 thr
// (2 CTAs/SM, 16 warps/SM). kq precomputed per chunk (5-shfl 2-value fold).

#define CSTEPS 16
#define L_SEQ  8192
#define NCH    (L_SEQ / CSTEPS)
#define DK     128

using ull = unsigned long long;

__device__ __forceinline__ ull pk(float lo, float hi) {
    ull r; asm("mov.b64 %0,{%1,%2};" : "=l"(r) : "f"(lo), "f"(hi)); return r;
}
__device__ __forceinline__ float hadd2(ull p) {
    float lo, hi; asm("mov.b64 {%0,%1},%2;" : "=f"(lo), "=f"(hi) : "l"(p));
    return lo + hi;
}
__device__ __forceinline__ ull mul2(ull a, ull b) {
    ull d; asm("mul.rn.f32x2 %0,%1,%2;" : "=l"(d) : "l"(a), "l"(b)); return d;
}
__device__ __forceinline__ ull fma2(ull a, ull b, ull c) {
    ull d; asm("fma.rn.f32x2 %0,%1,%2,%3;" : "=l"(d) : "l"(a), "l"(b), "l"(c)); return d;
}
__device__ __forceinline__ unsigned su32(const void* p) {
    return (unsigned)__cvta_generic_to_shared(p);
}
__device__ __forceinline__ void cp16(unsigned s, const void* g) {
    asm volatile("cp.async.cg.shared.global [%0],[%1],16;" :: "r"(s), "l"(g));
}
__device__ __forceinline__ void cp4(unsigned s, const void* g) {
    asm volatile("cp.async.ca.shared.global [%0],[%1],4;" :: "r"(s), "l"(g));
}
__device__ __forceinline__ void cp_commit() {
    asm volatile("cp.async.commit_group;" ::: "memory");
}
__device__ __forceinline__ void cp_wait_all() {
    asm volatile("cp.async.wait_group 0;" ::: "memory");
}
__device__ __forceinline__ float dot4(float4 a, float4 b) {
    return fmaf(a.x, b.x, fmaf(a.y, b.y, fmaf(a.z, b.z, a.w * b.w)));
}

__global__ __launch_bounds__(256, 2)
void titans_kernel(const float* __restrict__ Q,
                   const float* __restrict__ K,
                   const float* __restrict__ V,
                   float* __restrict__ Y) {
    static constexpr float cCP[16] = {  // 0.98^i
        1.0f, 0.98f, 0.9604f, 0.941192f, 0.92236816f, 0.9039207968f,
        0.8858423809f, 0.8681255332f, 0.8507630226f, 0.8337477621f,
        0.8170728069f, 0.8007313508f, 0.7847167237f, 0.7690223892f,
        0.7536419414f, 0.7385691035f };
    static constexpr float cCY[16] = {  // 0.98^(i+1)
        0.98f, 0.9604f, 0.941192f, 0.92236816f, 0.9039207968f, 0.8858423809f,
        0.8681255332f, 0.8507630226f, 0.8337477621f, 0.8170728069f,
        0.8007313508f, 0.7847167237f, 0.7690223892f, 0.7536419414f,
        0.7385691035f, 0.7237977214f };
    static constexpr float cS[16] = {   // -0.1*(0.9/0.98)^(i+1)
        -0.09183673469f, -0.08433985839f, -0.07745414463f, -0.07113064017f,
        -0.06532344097f, -0.05999029968f, -0.05509252418f, -0.05059456302f,
        -0.04646378542f, -0.04267021926f, -0.03918632342f, -0.03598663375f,
        -0.03304811221f, -0.03034970510f, -0.02787207213f, -0.02559670445f };
    static constexpr float cA[16] = {   // -0.02/0.98^(i+1)
        -0.02040816327f, -0.02082465640f, -0.02124964939f, -0.02168331570f,
        -0.02212583235f, -0.02257738015f, -0.02303814301f, -0.02350830920f,
        -0.02398807061f, -0.02447762307f, -0.02497716640f, -0.02548690449f,
        -0.02600704540f, -0.02653780143f, -0.02707938921f, -0.02763202981f };
    static constexpr float cB[16] = {   // 0.2/0.9^(i+1)
        0.2222222222f, 0.2469135802f, 0.2743484225f, 0.3048315805f,
        0.3387017561f, 0.3763352846f, 0.4181503162f, 0.4646114624f,
        0.5162349582f, 0.5735943980f, 0.6373271089f, 0.7081412321f,
        0.7868235912f, 0.8742484347f, 0.9713871497f, 1.0793190552f };
    static constexpr float cYS[16] = {  // cCY[i]*cS[i]
        -0.09000000000f, -0.08099999994f, -0.07289999992f, -0.06560999987f,
        -0.05904899992f, -0.05314409988f, -0.04782968990f, -0.04304672090f,
        -0.03874204881f, -0.03486784393f, -0.03138105953f, -0.02824295358f,
        -0.02541865822f, -0.02287679240f, -0.02058911316f, -0.01853020184f };
    constexpr float C16F = 0.7237977214f;   // 0.98^16
    constexpr float B16F = 0.1853020189f;   // 0.9^16

    __shared__ float kb[2][CSTEPS][DK];
    __shared__ float qb[2][CSTEPS][DK];
    __shared__ float vT[2][8][20];           // [row][step]
    __shared__ float yb[2][CSTEPS][8][4];    // [step][row][slot 1..3]
    __shared__ float skqs[16];               // k_t.q_t

    const int tid  = threadIdx.x;
    const int w    = tid >> 5;               // warp = row 0..7
    const int lane = tid & 31;

    const int b     = blockIdx.x >> 4;       // 16 batches
    const int vbase = (blockIdx.x & 15) << 3;// 16 groups x 8 rows

    const size_t base = (size_t)b * L_SEQ * DK;
    const float* gk = K + base;
    const float* gq = Q + base;
    const float* gv = V + base;
    float*       gy = Y + base;

    // state: lane owns What[w, 4*lane..+3], mhat same
    ull W01 = 0, W23 = 0, M01 = 0, M23 = 0;

    const bool amp1 = lane & 1;
    const bool amp2 = lane & 2;
    const int  src0 = lane & 28;             // class-0 lane of own 4-group

    // ---- preload chunk 0 ----
    {
        #pragma unroll
        for (int u = 0; u < 2; ++u) {
            int id = u * 256 + tid;
            cp16(su32(&kb[0][0][0]) + id * 16, gk + id * 4);
            cp16(su32(&qb[0][0][0]) + id * 16, gq + id * 4);
        }
        if (tid < 128) {
            int i = tid >> 3, j = tid & 7;
            cp4(su32(&vT[0][j][i]), gv + (size_t)i * DK + vbase + j);
        }
        cp_commit();
        cp_wait_all();
        __syncthreads();
    }

    for (int chunk = 0; chunk < NCH; ++chunk) {
        const int cur = chunk & 1;
        const int t0  = chunk * CSTEPS;

        // ---- kq prep: warp w handles steps w and w+8 (2-value fold) ----
        {
            const float4 ka = *(const float4*)&kb[cur][w][lane << 2];
            const float4 qa = *(const float4*)&qb[cur][w][lane << 2];
            const float4 kc = *(const float4*)&kb[cur][w + 8][lane << 2];
            const float4 qc = *(const float4*)&qb[cur][w + 8][lane << 2];
            float p0 = dot4(ka, qa);
            float p1 = dot4(kc, qc);
            float s  = amp1 ? p0 : p1;
            float rc = __shfl_xor_sync(0xffffffffu, s, 1);
            float m  = (amp1 ? p1 : p0) + rc;   // even lanes: p0, odd: p1
            m += __shfl_xor_sync(0xffffffffu, m, 2);
            m += __shfl_xor_sync(0xffffffffu, m, 4);
            m += __shfl_xor_sync(0xffffffffu, m, 8);
            m += __shfl_xor_sync(0xffffffffu, m, 16);
            if (lane == 0) skqs[w] = m;
            if (lane == 1) skqs[w + 8] = m;
        }

        // stage this warp's v row (broadcast LDS.128)
        float vreg[CSTEPS];
        #pragma unroll
        for (int jj = 0; jj < 4; ++jj)
            *(float4*)&vreg[jj * 4] = *(const float4*)&vT[cur][w][jj * 4];

        // prefetch next chunk
        if (chunk + 1 < NCH) {
            const int nb = cur ^ 1;
            const size_t nt = (size_t)(t0 + CSTEPS) * DK;
            #pragma unroll
            for (int u = 0; u < 2; ++u) {
                int id = u * 256 + tid;
                cp16(su32(&kb[nb][0][0]) + id * 16, gk + nt + id * 4);
                cp16(su32(&qb[nb][0][0]) + id * 16, gq + nt + id * 4);
            }
            if (tid < 128) {
                int i = tid >> 3, j = tid & 7;
                cp4(su32(&vT[nb][j][i]), gv + nt + (size_t)i * DK + vbase + j);
            }
        }
        cp_commit();

        __syncthreads();   // skqs visible

        // stage kq values (broadcast)
        float skqreg[CSTEPS];
        #pragma unroll
        for (int jj = 0; jj < 4; ++jj)
            *(float4*)&skqreg[jj * 4] = *(const float4*)&skqs[jj * 4];

        // ---- 16 sequential steps ----
        #pragma unroll
        for (int i = 0; i < CSTEPS; ++i) {
            const float4 k4 = *(const float4*)&kb[cur][i][lane << 2];
            const float4 q4 = *(const float4*)&qb[cur][i][lane << 2];
            const ull k01 = pk(k4.x, k4.y), k23 = pk(k4.z, k4.w);
            const ull q01 = pk(q4.x, q4.y), q23 = pk(q4.z, q4.w);

            // three dots on pre-update state (per-lane partials)
            float wk = hadd2(fma2(W01, k01, mul2(W23, k23)));
            float wq = hadd2(fma2(W01, q01, mul2(W23, q23)));
            float mq = hadd2(fma2(M01, q01, mul2(M23, q23)));

            // folded butterfly (R10, validated):
            // classes (lane&3): 0 = wk, 1 = wq, 2 = mq-even, 3 = mq-odd
            float send1 = amp1 ? wk : wq;
            float recv1 = __shfl_xor_sync(0xffffffffu, send1, 1);
            float a = (amp1 ? wq : wk) + recv1;
            float send2 = amp2 ? a : mq;
            float recv2 = __shfl_xor_sync(0xffffffffu, send2, 2);
            float c = (amp2 ? mq : a) + recv2;
            c += __shfl_xor_sync(0xffffffffu, c, 4);
            c += __shfl_xor_sync(0xffffffffu, c, 8);
            c += __shfl_xor_sync(0xffffffffu, c, 16);
            const float wkall = __shfl_sync(0xffffffffu, c, src0);

            const float r  = fmaf(cCP[i], wkall, -vreg[i]);
            const float ta = cA[i] * r;
            const float tb = cB[i] * r;
            const ull a2 = pk(ta, ta);
            const ull b2 = pk(tb, tb);
            const ull s2 = pk(cS[i], cS[i]);

            // y partials: lane1 holds wq, lanes 2/3 hold mq halves.
            //   y = cCY*(wq + ta*kq) + cCY*cS*mq_e + cCY*cS*mq_o
            if (lane >= 1 && lane <= 3) {
                float val = (lane == 1)
                    ? cCY[i] * fmaf(ta, skqreg[i], c)
                    : cYS[i] * c;
                yb[cur][i][w][lane] = val;
            }

            // W += s*m + a*k ; m += b*k   (pre-update m used for W)
            W01 = fma2(s2, M01, W01); W01 = fma2(a2, k01, W01);
            M01 = fma2(b2, k01, M01);
            W23 = fma2(s2, M23, W23); W23 = fma2(a2, k23, W23);
            M23 = fma2(b2, k23, M23);
        }

        // chunk-end rescale
        {
            const ull c16 = pk(C16F, C16F);
            const ull b16 = pk(B16F, B16F);
            W01 = mul2(c16, W01); W23 = mul2(c16, W23);
            M01 = mul2(b16, M01); M23 = mul2(b16, M23);
        }

        cp_wait_all();
        __syncthreads();

        // writeback this chunk's y (sum the 3 partials)
        if (tid < 128) {
            int i = tid >> 3, j = tid & 7;
            const float4 p = *(const float4*)&yb[cur][i][j][0];
            gy[(size_t)(t0 + i) * DK + vbase + j] = p.y + p.z + p.w;
        }
    }
}

extern "C" void kernel_launch(void* const* d_in, const int* in_sizes, int n_in,
                              void* d_out, int out_size) {
    const float* Q = (const float*)d_in[0];
    const float* K = (const float*)d_in[1];
    const float* V = (const float*)d_in[2];
    float* Y = (float*)d_out;
    (void)in_sizes; (void)n_in; (void)out_size;
    titans_kernel<<<256, 256>>>(Q, K, V, Y);
}